// round 4
// baseline (speedup 1.0000x reference)
#include <cuda_runtime.h>
#include <cstdint>

#define Bk 128
#define Sk 128
#define Ek 256
#define Dk 512
#define Kk 16
#define Lk 1906
#define Rk 2033
#define Tk 127
#define TINYF 1.17549435e-38f

__device__ float g_h[2][Bk][Dk];
__device__ float g_x[Bk][Dk];
__device__ float g_last_t[Bk];
__device__ int   g_last_m[Bk];
__device__ int   g_chosen[Bk];
__device__ int   g_cand[Bk][Lk];
__device__ float g_prob[Bk][Lk];
__device__ float g_nrec[Bk][Rk];
__device__ unsigned g_cnt[4][32];   // per-group barrier counters, 128B apart

// JAX threefry2x32 (exact)
__device__ __forceinline__ void tf2x32(uint32_t k0, uint32_t k1,
                                       uint32_t x0, uint32_t x1,
                                       uint32_t& o0, uint32_t& o1) {
  uint32_t ks2 = k0 ^ k1 ^ 0x1BD11BDAu;
  x0 += k0; x1 += k1;
#define RR(d) { x0 += x1; x1 = (x1 << d) | (x1 >> (32 - d)); x1 ^= x0; }
  RR(13) RR(15) RR(26) RR(6)  x0 += k1;  x1 += ks2 + 1u;
  RR(17) RR(29) RR(16) RR(24) x0 += ks2; x1 += k0 + 2u;
  RR(13) RR(15) RR(26) RR(6)  x0 += k0;  x1 += k1 + 3u;
  RR(17) RR(29) RR(16) RR(24) x0 += k1;  x1 += ks2 + 4u;
  RR(13) RR(15) RR(26) RR(6)  x0 += ks2; x1 += k0 + 5u;
#undef RR
  o0 = x0; o1 = x1;
}

__global__ void reset_kernel() {
  if (threadIdx.x < 128) ((unsigned*)g_cnt)[threadIdx.x] = 0u;
}

// 32-block group barrier (sense via monotone counter)
__device__ __forceinline__ void gbar(int bc, unsigned& epoch) {
  __syncthreads();
  if (threadIdx.x == 0) {
    __threadfence();
    epoch += 32u;
    atomicAdd(&g_cnt[bc][0], 1u);
    while (*((volatile unsigned*)&g_cnt[bc][0]) < epoch) { }
    __threadfence();
  }
  __syncthreads();
}

__global__ void __launch_bounds__(256, 1)
rnn_persistent(const int* __restrict__ marker,
               const float* __restrict__ timed,
               const float* __restrict__ maskd,
               const float* __restrict__ emb,
               const int* __restrict__ nlist,
               const float* __restrict__ nprob,
               const float* __restrict__ W_te,
               const float* __restrict__ b_te,
               const float* __restrict__ W_el,
               const float* __restrict__ b_el,
               const float* __restrict__ W_ih,
               const float* __restrict__ b_ih,
               const float* __restrict__ W_hh,
               const float* __restrict__ b_hh,
               const float* __restrict__ W_time,
               const float* __restrict__ b_time,
               const float* __restrict__ W_mk,
               const float* __restrict__ b_mk,
               float* __restrict__ out) {
  extern __shared__ __align__(16) float SM[];
  const int BID = blockIdx.x;
  const int tid = threadIdx.x;
  const int bc = BID >> 5;    // group / batch tile (32 rows)
  const int dc = BID & 31;    // d tile (16 cols)
  const int myb = BID;        // phase-C row
  unsigned epoch = 0;

  // ---------------- init (each block its own row) ----------------
  for (int l = tid; l < Lk; l += 256) {
    g_prob[myb][l] = (l == 0) ? 1.0f : 0.0f;
    g_cand[myb][l] = (l == 0) ? marker[myb * Sk] : 0;
  }
  for (int r = tid; r < Rk; r += 256) g_nrec[myb][r] = 1.0f;
  for (int d = tid; d < Dk; d += 256) g_h[0][myb][d] = 0.0f;
  if (tid == 0) {
    g_last_t[myb] = timed[myb * Sk];
    g_last_m[myb] = marker[myb * Sk];
    g_chosen[myb] = 0;
    out[0 * 16384 + myb * Sk] = (float)marker[myb * Sk];
    out[1 * 16384 + myb * Sk] = timed[myb * Sk];
    out[2 * 16384 + myb * Sk] = maskd[myb * Sk];
    out[3 * 16384 + myb * Sk] = 1.0f;
    out[4 * 16384 + myb * Sk] = 1.0f;
  }
  gbar(bc, epoch);

  for (int t = 0; t < Tk; t++) {
    // ============ Phase A: x = leaky(vec @ W_el + b_el) ============
    {
      float* sV = SM;  // [32][257]
      int e = tid;
      float wte = W_te[e], bte = b_te[e];
#pragma unroll 4
      for (int bl = 0; bl < 32; bl++) {
        int b = bc * 32 + bl;
        float te = __fadd_rn(__fmul_rn(g_last_t[b], wte), bte);
        sV[bl * 257 + e] = __fadd_rn(emb[(size_t)g_last_m[b] * Ek + e],
                                     __fmul_rn(0.1f, te));
      }
      __syncthreads();
      int dl = tid & 15, bh = tid >> 4;
      int d = dc * 16 + dl;
      const float* wp = W_el + d;
      const float* v0 = sV + bh * 257;
      const float* v1 = sV + (bh + 16) * 257;
      float a0 = 0.0f, a1 = 0.0f;
#pragma unroll 8
      for (int e2 = 0; e2 < Ek; e2++) {
        float w = wp[e2 * Dk];
        a0 = fmaf(v0[e2], w, a0);
        a1 = fmaf(v1[e2], w, a1);
      }
      float bb = b_el[d];
      a0 = __fadd_rn(a0, bb);
      a1 = __fadd_rn(a1, bb);
      g_x[(bc * 32 + bh)][d]      = (a0 >= 0.0f) ? a0 : __fmul_rn(0.01f, a0);
      g_x[(bc * 32 + bh + 16)][d] = (a1 >= 0.0f) ? a1 : __fmul_rn(0.01f, a1);
    }
    gbar(bc, epoch);

    // ============ Phase B: h = tanh(x@W_ih + b_ih + h@W_hh + b_hh) ============
    {
      float* sx = SM;                 // [32][520]
      float* sh = SM + 32 * 520;      // [32][520]
      const float* hin = &g_h[t & 1][0][0];
      // one-shot staging: 32 rows x 512 of x and h
#pragma unroll
      for (int i = tid * 4; i < 32 * 512; i += 256 * 4) {
        int r = i >> 9, c = i & 511;
        float4 xv = *(const float4*)&g_x[bc * 32 + r][c];
        float4 hv = *(const float4*)&hin[(bc * 32 + r) * Dk + c];
        *(float4*)&sx[r * 520 + c] = xv;
        *(float4*)&sh[r * 520 + c] = hv;
      }
      __syncthreads();
      int dp = tid & 7, bl = tid >> 3;
      int b = bc * 32 + bl;
      int d0 = dc * 16 + dp * 2;
      const float* wi = W_ih + d0;
      const float* wh = W_hh + d0;
      const float* px = sx + bl * 520;
      const float* ph = sh + bl * 520;
      float ax0 = 0, ax1 = 0, ah0 = 0, ah1 = 0;
#pragma unroll 4
      for (int e4 = 0; e4 < 512; e4 += 4) {
        float4 xv = *(const float4*)(px + e4);
        float4 hv = *(const float4*)(ph + e4);
        {
          float2 w1 = *(const float2*)(wi + (e4 + 0) * Dk);
          float2 w2 = *(const float2*)(wh + (e4 + 0) * Dk);
          ax0 = fmaf(xv.x, w1.x, ax0); ax1 = fmaf(xv.x, w1.y, ax1);
          ah0 = fmaf(hv.x, w2.x, ah0); ah1 = fmaf(hv.x, w2.y, ah1);
        }
        {
          float2 w1 = *(const float2*)(wi + (e4 + 1) * Dk);
          float2 w2 = *(const float2*)(wh + (e4 + 1) * Dk);
          ax0 = fmaf(xv.y, w1.x, ax0); ax1 = fmaf(xv.y, w1.y, ax1);
          ah0 = fmaf(hv.y, w2.x, ah0); ah1 = fmaf(hv.y, w2.y, ah1);
        }
        {
          float2 w1 = *(const float2*)(wi + (e4 + 2) * Dk);
          float2 w2 = *(const float2*)(wh + (e4 + 2) * Dk);
          ax0 = fmaf(xv.z, w1.x, ax0); ax1 = fmaf(xv.z, w1.y, ax1);
          ah0 = fmaf(hv.z, w2.x, ah0); ah1 = fmaf(hv.z, w2.y, ah1);
        }
        {
          float2 w1 = *(const float2*)(wi + (e4 + 3) * Dk);
          float2 w2 = *(const float2*)(wh + (e4 + 3) * Dk);
          ax0 = fmaf(xv.w, w1.x, ax0); ax1 = fmaf(xv.w, w1.y, ax1);
          ah0 = fmaf(hv.w, w2.x, ah0); ah1 = fmaf(hv.w, w2.y, ah1);
        }
      }
      float bi0 = b_ih[d0], bi1 = b_ih[d0 + 1];
      float bh0 = b_hh[d0], bh1 = b_hh[d0 + 1];
      float* hout = &g_h[(t + 1) & 1][0][0];
      hout[b * Dk + d0]     = tanhf(__fadd_rn(__fadd_rn(__fadd_rn(ax0, bi0), ah0), bh0));
      hout[b * Dk + d0 + 1] = tanhf(__fadd_rn(__fadd_rn(__fadd_rn(ax1, bi1), ah1), bh1));
    }
    gbar(bc, epoch);

    // ============ Phase C: sampling step for row myb ============
    {
      float* sE = SM;                     // [16][256]
      float* hb = SM + 4096;              // [512]
      float* red = SM + 4608;             // [8] warp partials (sum)
      float* redv = SM + 4624;            // [8] warp partials (argmax val)
      int*   ri   = (int*)(SM + 4640);    // [8]
      int*   s_neigh = (int*)(SM + 4656); // [16]
      float* s_score = SM + 4672;         // [16]
      int warp = tid >> 5, lane = tid & 31;

      hb[tid] = g_h[(t + 1) & 1][myb][tid];
      hb[tid + 256] = g_h[(t + 1) & 1][myb][tid + 256];
      int lm = g_last_m[myb];
      if (tid < Kk) {
        s_neigh[tid] = nlist[lm * Kk + tid];
        g_nrec[myb][1 + t * Kk + tid] = nprob[lm * Kk + tid];
      }
      __syncthreads();

      // stage emb rows of the 16 neighbors
      {
        int e = tid;
#pragma unroll 4
        for (int k = 0; k < Kk; k++)
          sE[k * 256 + e] = emb[(size_t)s_neigh[k] * Ek + e];
      }

      // dt partial + warp-shuffle reduce
      {
        float a = __fmul_rn(hb[2 * tid], W_time[2 * tid]);
        a = fmaf(hb[2 * tid + 1], W_time[2 * tid + 1], a);
        for (int o = 16; o; o >>= 1) a = __fadd_rn(a, __shfl_down_sync(0xffffffffu, a, o));
        if (lane == 0) red[warp] = a;
      }
      __syncthreads();

      // neighbor scores: dot([emb[neigh], h], W_mk) + b_mk  (len 768)
      for (int k = warp; k < Kk; k += 8) {
        const float* ev = sE + k * 256;
        float acc = 0.0f;
        for (int i = lane; i < Ek + Dk; i += 32) {
          float v = (i < Ek) ? ev[i] : hb[i - Ek];
          acc = fmaf(v, W_mk[i], acc);
        }
        for (int o = 16; o; o >>= 1) acc += __shfl_down_sync(0xffffffffu, acc, o);
        if (lane == 0) s_score[k] = __fadd_rn(acc, b_mk[0]);
      }

      float newt = 0.0f;
      if (tid == 0) {
        float s = red[0];
        for (int w = 1; w < 8; w++) s = __fadd_rn(s, red[w]);
        float xx = __fadd_rn(s, b_time[0]);
        float sp = __fadd_rn(fmaxf(xx, 0.0f), log1pf(expf(-fabsf(xx))));
        newt = __fadd_rn(g_last_t[myb], sp);
      }
      __syncthreads();

      if (tid == 0) {
        float mx = s_score[0];
        for (int k = 1; k < Kk; k++) mx = fmaxf(mx, s_score[k]);
        float ee[Kk]; float ssum = 0.0f;
        for (int k = 0; k < Kk; k++) {
          ee[k] = expf(__fadd_rn(s_score[k], -mx));
          ssum = __fadd_rn(ssum, ee[k]);
        }
        int ch = g_chosen[myb];
        float cp = g_prob[myb][ch];
        g_prob[myb][ch] = __fmul_rn(cp, __fdiv_rn(ee[0], ssum));
        int base = 1 + t * (Kk - 1);
        for (int k = 1; k < Kk; k++) {
          g_prob[myb][base + k - 1] = __fmul_rn(cp, __fdiv_rn(ee[k], ssum));
          g_cand[myb][base + k - 1] = s_neigh[k];
        }
      }
      __syncthreads();

      // gumbel-max over the active prefix (prob==0 beyond -> exactly -1e30)
      uint32_t k0, k1;
      tf2x32(0u, 42u, 0u, (uint32_t)t, k0, k1);
      int active = 15 * t + 16;
      if (active > Lk) active = Lk;
      float bv = -3.4e38f; int bi = 0x7fffffff;
      for (int l = tid; l < active; l += 256) {
        float pr = g_prob[myb][l];
        float logit = (pr > 0.0f) ? logf(fmaxf(pr, 1e-38f)) : -1e30f;
        uint32_t i = (uint32_t)(myb * Lk + l);
        uint32_t o0, o1;
        tf2x32(k0, k1, 0u, i, o0, o1);
        uint32_t bits = o0 ^ o1;
        float u0 = __fadd_rn(__uint_as_float((bits >> 9) | 0x3f800000u), -1.0f);
        float u = fmaxf(TINYF, __fadd_rn(u0, TINYF));
        float gq = -logf(-logf(u));
        float v = __fadd_rn(logit, gq);
        if (v > bv) { bv = v; bi = l; }
      }
      for (int o = 16; o; o >>= 1) {
        float ov = __shfl_down_sync(0xffffffffu, bv, o);
        int   oi = __shfl_down_sync(0xffffffffu, bi, o);
        if (ov > bv || (ov == bv && oi < bi)) { bv = ov; bi = oi; }
      }
      if (lane == 0) { redv[warp] = bv; ri[warp] = bi; }
      __syncthreads();

      if (tid == 0) {
        float bestv = redv[0]; int besti = ri[0];
        for (int w = 1; w < 8; w++) {
          if (redv[w] > bestv || (redv[w] == bestv && ri[w] < besti)) {
            bestv = redv[w]; besti = ri[w];
          }
        }
        int nm = g_cand[myb][besti];
        float snp = g_nrec[myb][besti];
        float ssp = g_prob[myb][besti];
        int col = t + 1;
        out[0 * 16384 + myb * Sk + col] = (float)nm;
        out[1 * 16384 + myb * Sk + col] = newt;
        out[2 * 16384 + myb * Sk + col] = (newt < 1000.0f) ? 1.0f : 0.0f;
        out[3 * 16384 + myb * Sk + col] = snp;
        out[4 * 16384 + myb * Sk + col] = ssp;
        g_chosen[myb] = besti;
        g_last_m[myb] = nm;
        g_last_t[myb] = newt;
      }
    }
    gbar(bc, epoch);
  }
}

extern "C" void kernel_launch(void* const* d_in, const int* in_sizes, int n_in,
                              void* d_out, int out_size) {
  const int*   marker = (const int*)d_in[0];
  const float* timed  = (const float*)d_in[1];
  const float* maskd  = (const float*)d_in[2];
  const float* emb    = (const float*)d_in[3];
  const int*   nlist  = (const int*)d_in[4];
  const float* nprob  = (const float*)d_in[5];
  const float* W_te   = (const float*)d_in[6];
  const float* b_te   = (const float*)d_in[7];
  const float* W_el   = (const float*)d_in[8];
  const float* b_el   = (const float*)d_in[9];
  const float* W_ih   = (const float*)d_in[10];
  const float* b_ih   = (const float*)d_in[11];
  const float* W_hh   = (const float*)d_in[12];
  const float* b_hh   = (const float*)d_in[13];
  const float* W_time = (const float*)d_in[14];
  const float* b_time = (const float*)d_in[15];
  const float* W_mk   = (const float*)d_in[16];
  const float* b_mk   = (const float*)d_in[17];
  float* out = (float*)d_out;

  static int smem_set = 0;
  const int SMEM_BYTES = 2 * 32 * 520 * 4;  // 133120
  if (!smem_set) {
    cudaFuncSetAttribute(rnn_persistent,
                         cudaFuncAttributeMaxDynamicSharedMemorySize, SMEM_BYTES);
    smem_set = 1;
  }
  reset_kernel<<<1, 128>>>();
  rnn_persistent<<<128, 256, SMEM_BYTES>>>(marker, timed, maskd, emb, nlist, nprob,
                                           W_te, b_te, W_el, b_el, W_ih, b_ih,
                                           W_hh, b_hh, W_time, b_time, W_mk, b_mk, out);
}